// round 8
// baseline (speedup 1.0000x reference)
#include <cuda_runtime.h>
#include <cuda_bf16.h>
#include <math.h>

// Problem constants
#define EMBED  1024
#define INDIM  256
#define HID    256
#define NVIEW  6
#define NROWS  49152   // B*M*NVIEW
#define NBM    8192    // B*M

#define LDSK32 20              // u32 per smem row (32 data bf16-pairs + pad)
#define STAGE_U32 (128 * LDSK32)

// Scratch (allocation-free: __device__ globals)
__device__ float g_bufA[(size_t)NROWS * EMBED];        // GEMM1 out / gates
__device__ float g_bufX[2 * (size_t)NROWS * INDIM];    // ping-pong activations
__device__ float g_h2[2 * NBM * HID];                  // ping-pong hidden
__device__ float g_c[NBM * HID];
__device__ float g_score[NBM];
__device__ float g_WihP[3 * 1024 * 256];               // permuted weights
__device__ float g_WhhP[3 * 1024 * 256];
__device__ float g_biasP[3 * 1024];                    // bih+bhh permuted

__device__ __forceinline__ void mma16816(float* d, const unsigned* a, const unsigned* b)
{
    asm volatile(
        "mma.sync.aligned.m16n8k16.row.col.f32.bf16.bf16.f32 "
        "{%0,%1,%2,%3}, {%4,%5,%6,%7}, {%8,%9}, {%0,%1,%2,%3};\n"
        : "+f"(d[0]), "+f"(d[1]), "+f"(d[2]), "+f"(d[3])
        : "r"(a[0]), "r"(a[1]), "r"(a[2]), "r"(a[3]), "r"(b[0]), "r"(b[1]));
}

__device__ __forceinline__ void ldsm_x4(unsigned& r0, unsigned& r1, unsigned& r2,
                                        unsigned& r3, unsigned addr)
{
    asm volatile("ldmatrix.sync.aligned.m8n8.x4.shared.b16 {%0,%1,%2,%3}, [%4];\n"
                 : "=r"(r0), "=r"(r1), "=r"(r2), "=r"(r3) : "r"(addr));
}

__device__ __forceinline__ void cvt_store(unsigned* S32, int row, int kc, float4 v)
{
    __nv_bfloat16 hx = __float2bfloat16_rn(v.x);
    __nv_bfloat16 hy = __float2bfloat16_rn(v.y);
    __nv_bfloat16 hz = __float2bfloat16_rn(v.z);
    __nv_bfloat16 hw = __float2bfloat16_rn(v.w);
    __nv_bfloat162 h01; h01.x = hx; h01.y = hy;
    __nv_bfloat162 h23; h23.x = hz; h23.y = hw;
    __nv_bfloat162 l01;
    l01.x = __float2bfloat16_rn(v.x - __bfloat162float(hx));
    l01.y = __float2bfloat16_rn(v.y - __bfloat162float(hy));
    __nv_bfloat162 l23;
    l23.x = __float2bfloat16_rn(v.z - __bfloat162float(hz));
    l23.y = __float2bfloat16_rn(v.w - __bfloat162float(hw));
    const int base = row * LDSK32 + (kc >> 1);
    uint2 hi; hi.x = *reinterpret_cast<unsigned*>(&h01); hi.y = *reinterpret_cast<unsigned*>(&h23);
    uint2 lo; lo.x = *reinterpret_cast<unsigned*>(&l01); lo.y = *reinterpret_cast<unsigned*>(&l23);
    *reinterpret_cast<uint2*>(S32 + base)     = hi;
    *reinterpret_cast<uint2*>(S32 + base + 8) = lo;
}

// ---------------------------------------------------------------------------
// C = A @ B^T via bf16x3-split tensor-core MMA. Tile 128x128x16, 8 warps
// (2Mx4N), warp tile 64x32. Double-buffered smem, ldmatrix fragment loads.
// EPI 0: C = resid + gelu_exact(acc+bias0)
// EPI 1: C = acc+bias0
// EPI 4: LSTM input-proj (permuted gates): v=acc+bias0. Rows with t==0 run the
//        cell (cold=0) writing Hout/Cst/Xout; other rows store gates to C.
// EPI 5: LSTM recurrent: v = acc + C (read-only). Cell for all rows at t=tparam;
//        writes Hout/Cst/Xout. Nothing stored to C.
// Permuted layout: col p = 4*j + gate, gate in {i,f,g,o}.
// ---------------------------------------------------------------------------
template <int EPI>
__global__ __launch_bounds__(256, 2) void bgemm_kernel(
    const float* __restrict__ A, int lda,
    const float* __restrict__ B, int ldb,
    float* __restrict__ C, int ldc,
    int K,
    const float* __restrict__ bias0,
    const float* __restrict__ resid,
    float* __restrict__ Hout,
    float* __restrict__ Cst,
    float* __restrict__ Xout,
    int tparam)
{
    __shared__ __align__(16) unsigned As32[2 * STAGE_U32];
    __shared__ __align__(16) unsigned Bs32[2 * STAGE_U32];

    const int tid  = threadIdx.x;
    const int bx   = blockIdx.x;
    const int by   = blockIdx.y;
    const int warp = tid >> 5;
    const int lane = tid & 31;
    const int g    = lane >> 2;
    const int tg   = lane & 3;
    const int warpM = (warp & 1) * 64;
    const int warpN = (warp >> 1) * 32;

    const int lrow = tid >> 2;
    const int kc   = (tid & 3) * 4;

    const float* Ap = A + (size_t)(by * 128 + lrow) * lda + kc;
    const float* Bp = B + (size_t)(bx * 128 + lrow) * ldb + kc;

    const unsigned asmem = (unsigned)__cvta_generic_to_shared(As32);
    const unsigned bsmem = (unsigned)__cvta_generic_to_shared(Bs32);
    unsigned aAddr[4], bAddr[2];
#pragma unroll
    for (int mt = 0; mt < 4; mt++) {
        const int r = warpM + mt * 16 + (lane & 15);
        aAddr[mt] = asmem + r * (LDSK32 * 4) + ((lane >> 4) & 1) * 16;
    }
#pragma unroll
    for (int p = 0; p < 2; p++) {
        const int r = warpN + p * 16 + (lane & 7) + ((lane >> 4) & 1) * 8;
        bAddr[p] = bsmem + r * (LDSK32 * 4) + ((lane >> 3) & 1) * 16;
    }

    float acc[4][4][4];
#pragma unroll
    for (int mt = 0; mt < 4; mt++)
#pragma unroll
        for (int nt = 0; nt < 4; nt++)
#pragma unroll
            for (int e = 0; e < 4; e++) acc[mt][nt][e] = 0.f;

    float4 pa0 = *reinterpret_cast<const float4*>(Ap);
    float4 pa1 = *reinterpret_cast<const float4*>(Ap + (size_t)64 * lda);
    float4 pb0 = *reinterpret_cast<const float4*>(Bp);
    float4 pb1 = *reinterpret_cast<const float4*>(Bp + (size_t)64 * ldb);
    cvt_store(As32, lrow,      kc, pa0);
    cvt_store(As32, lrow + 64, kc, pa1);
    cvt_store(Bs32, lrow,      kc, pb0);
    cvt_store(Bs32, lrow + 64, kc, pb1);
    __syncthreads();

    int stage = 0;
    for (int k0 = 0; k0 < K; k0 += 16) {
        const bool hasNext = (k0 + 16 < K);
        if (hasNext) {
            pa0 = *reinterpret_cast<const float4*>(Ap + k0 + 16);
            pa1 = *reinterpret_cast<const float4*>(Ap + (size_t)64 * lda + k0 + 16);
            pb0 = *reinterpret_cast<const float4*>(Bp + k0 + 16);
            pb1 = *reinterpret_cast<const float4*>(Bp + (size_t)64 * ldb + k0 + 16);
        }

        const unsigned soff = stage * (STAGE_U32 * 4);
#pragma unroll
        for (int s = 0; s < 3; s++) {
            const unsigned ao = (s == 1) ? 32u : 0u;
            const unsigned bo = (s == 2) ? 32u : 0u;
            unsigned af[4][4], bfr[4][2];
#pragma unroll
            for (int mt = 0; mt < 4; mt++)
                ldsm_x4(af[mt][0], af[mt][1], af[mt][2], af[mt][3],
                        aAddr[mt] + soff + ao);
            ldsm_x4(bfr[0][0], bfr[0][1], bfr[1][0], bfr[1][1], bAddr[0] + soff + bo);
            ldsm_x4(bfr[2][0], bfr[2][1], bfr[3][0], bfr[3][1], bAddr[1] + soff + bo);
#pragma unroll
            for (int mt = 0; mt < 4; mt++)
#pragma unroll
                for (int nt = 0; nt < 4; nt++)
                    mma16816(acc[mt][nt], af[mt], bfr[nt]);
        }

        if (hasNext) {
            unsigned* An = As32 + (stage ^ 1) * STAGE_U32;
            unsigned* Bn = Bs32 + (stage ^ 1) * STAGE_U32;
            cvt_store(An, lrow,      kc, pa0);
            cvt_store(An, lrow + 64, kc, pa1);
            cvt_store(Bn, lrow,      kc, pb0);
            cvt_store(Bn, lrow + 64, kc, pb1);
            stage ^= 1;
            __syncthreads();
        }
    }

    if (EPI == 4 || EPI == 5) {
        // LSTM fused epilogue. Pair exchange: even tg holds (i,f), odd holds (g,o).
#pragma unroll
        for (int mt = 0; mt < 4; mt++) {
#pragma unroll
            for (int half = 0; half < 2; half++) {
                const int gr = by * 128 + warpM + mt * 16 + g + half * 8;
                int bm, t;
                if (EPI == 5) { bm = gr; t = tparam; }
                else          { bm = gr / 6; t = gr - bm * 6; }
                const bool docell = (EPI == 5) || (t == 0);
#pragma unroll
                for (int nt = 0; nt < 4; nt++) {
                    const int colbase = bx * 128 + warpN + nt * 8;
                    const int gc = colbase + tg * 2;
                    float v0 = acc[mt][nt][half * 2 + 0];
                    float v1 = acc[mt][nt][half * 2 + 1];
                    if (EPI == 4) {
                        v0 += bias0[gc]; v1 += bias0[gc + 1];
                    } else {
                        const float2 old = *reinterpret_cast<const float2*>(
                            C + (size_t)gr * ldc + gc);
                        v0 += old.x; v1 += old.y;
                    }
                    const float p0 = __shfl_xor_sync(0xFFFFFFFFu, v0, 1);
                    const float p1 = __shfl_xor_sync(0xFFFFFFFFu, v1, 1);
                    if (!docell) {
                        if (EPI == 4) {
                            float2 st; st.x = v0; st.y = v1;
                            *reinterpret_cast<float2*>(C + (size_t)gr * ldc + gc) = st;
                        }
                    } else if ((tg & 1) == 0) {
                        const int u = (colbase >> 2) + (tg >> 1);
                        const float si = 1.f / (1.f + expf(-v0));
                        const float sf = 1.f / (1.f + expf(-v1));
                        const float so = 1.f / (1.f + expf(-p1));
                        const float cold = (EPI == 5) ? Cst[bm * 256 + u] : 0.f;
                        const float cn = sf * cold + si * tanhf(p0);
                        const float hn = so * tanhf(cn);
                        Cst[bm * 256 + u]  = cn;
                        Hout[bm * 256 + u] = hn;
                        Xout[(size_t)(bm * 6 + t) * 256 + u] = hn;
                    }
                }
            }
        }
        return;
    }

    // EPI 0/1 epilogue (float2-vectorized)
#pragma unroll
    for (int mt = 0; mt < 4; mt++) {
#pragma unroll
        for (int nt = 0; nt < 4; nt++) {
            const float* d = acc[mt][nt];
            const int gc = bx * 128 + warpN + nt * 8 + tg * 2;
#pragma unroll
            for (int half = 0; half < 2; half++) {
                const int gr = by * 128 + warpM + mt * 16 + g + half * 8;
                float* cp = C + (size_t)gr * ldc + gc;
                float2 v; v.x = d[half * 2]; v.y = d[half * 2 + 1];
                v.x += bias0[gc]; v.y += bias0[gc + 1];
                if (EPI == 0) {
                    float2 rs = *reinterpret_cast<const float2*>(
                        resid + (size_t)gr * ldc + gc);
                    v.x = 0.5f * v.x * (1.f + erff(v.x * 0.70710678118654752f)) + rs.x;
                    v.y = 0.5f * v.y * (1.f + erff(v.y * 0.70710678118654752f)) + rs.y;
                }
                *reinterpret_cast<float2*>(cp) = v;
            }
        }
    }
}

// Permute LSTM weights to gate-interleaved layout: p = 4*j + gate.
// orig row = (p&3)*256 + (p>>2). Also pre-sum bih+bhh.
__global__ __launch_bounds__(256) void permute_kernel(
    const float* __restrict__ Wih, const float* __restrict__ Whh,
    const float* __restrict__ bih, const float* __restrict__ bhh,
    float* __restrict__ WihP, float* __restrict__ WhhP, float* __restrict__ biasP)
{
    const int row = blockIdx.x;       // 0..3071 = l*1024 + p
    const int tid = threadIdx.x;      // 0..255
    const int l = row >> 10, p = row & 1023;
    const int orig = (p & 3) * 256 + (p >> 2);
    const size_t src = ((size_t)l * 1024 + orig) * 256;
    const size_t dst = (size_t)row * 256;
    WihP[dst + tid] = Wih[src + tid];
    WhhP[dst + tid] = Whh[src + tid];
    if (tid == 0) biasP[row] = bih[l * 1024 + orig] + bhh[l * 1024 + orig];
}

__global__ __launch_bounds__(256) void final1_kernel(
    const float* __restrict__ X, const float* __restrict__ Wv,
    const float* __restrict__ bv, const float* __restrict__ Ws,
    const float* __restrict__ bs, float* __restrict__ score)
{
    const int warp = threadIdx.x >> 5;
    const int lane = threadIdx.x & 31;
    const int bm = blockIdx.x * 8 + warp;
    float wv[8];
#pragma unroll
    for (int u = 0; u < 8; u++) wv[u] = Wv[lane + u * 32];
    float acc = 0.f;
#pragma unroll
    for (int t = 0; t < 6; t++) {
        const float* row = X + (size_t)(bm * 6 + t) * 256;
        float p = 0.f;
#pragma unroll
        for (int u = 0; u < 8; u++) p = fmaf(row[lane + u * 32], wv[u], p);
#pragma unroll
        for (int o = 16; o; o >>= 1) p += __shfl_xor_sync(0xFFFFFFFFu, p, o);
        acc = fmaf(Ws[t], p + bv[0], acc);
    }
    if (lane == 0) score[bm] = acc + bs[0];
}

__global__ __launch_bounds__(256) void final2_kernel(
    const float* __restrict__ score, float* __restrict__ out)
{
    __shared__ float s[256];
    s[threadIdx.x] = score[blockIdx.x * 256 + threadIdx.x];
    __syncthreads();
    for (int o = 128; o; o >>= 1) {
        if (threadIdx.x < o) s[threadIdx.x] += s[threadIdx.x + o];
        __syncthreads();
    }
    if (threadIdx.x == 0) out[blockIdx.x] = s[0] * (1.f / 256.f);
}

extern "C" void kernel_launch(void* const* d_in, const int* in_sizes, int n_in,
                              void* d_out, int out_size)
{
    (void)in_sizes; (void)n_in; (void)out_size;
    const float* swin = (const float*)d_in[0];
    const float* conv = (const float*)d_in[1];
    const float* Wc   = (const float*)d_in[2];
    const float* bc   = (const float*)d_in[3];
    const float* Win  = (const float*)d_in[4];
    const float* b_in = (const float*)d_in[5];
    const float* Wih  = (const float*)d_in[6];
    const float* Whh  = (const float*)d_in[7];
    const float* bih  = (const float*)d_in[8];
    const float* bhh  = (const float*)d_in[9];
    const float* Wv   = (const float*)d_in[10];
    const float* bv   = (const float*)d_in[11];
    const float* Ws   = (const float*)d_in[12];
    const float* bs   = (const float*)d_in[13];
    float* out = (float*)d_out;

    float *bufA, *bufX, *h2, *c, *score, *WihP, *WhhP, *biasP;
    cudaGetSymbolAddress((void**)&bufA, g_bufA);
    cudaGetSymbolAddress((void**)&bufX, g_bufX);
    cudaGetSymbolAddress((void**)&h2, g_h2);
    cudaGetSymbolAddress((void**)&c, g_c);
    cudaGetSymbolAddress((void**)&score, g_score);
    cudaGetSymbolAddress((void**)&WihP, g_WihP);
    cudaGetSymbolAddress((void**)&WhhP, g_WhhP);
    cudaGetSymbolAddress((void**)&biasP, g_biasP);

    float* X0 = bufX;
    float* X1 = bufX + (size_t)NROWS * INDIM;

    // 0) permute LSTM weights (independent of GEMM1/2; run first)
    permute_kernel<<<3072, 256>>>(Wih, Whh, bih, bhh, WihP, WhhP, biasP);

    // 1) bufA = swin + gelu(conv @ Wc^T + bc)   [49152,1024]
    bgemm_kernel<0><<<dim3(EMBED / 128, NROWS / 128), 256>>>(
        conv, EMBED, Wc, EMBED, bufA, EMBED, EMBED, bc, swin,
        nullptr, nullptr, nullptr, 0);

    // 2) X0 = bufA @ Win^T + b_in               [49152,256]
    bgemm_kernel<1><<<dim3(INDIM / 128, NROWS / 128), 256>>>(
        bufA, EMBED, Win, EMBED, X0, INDIM, EMBED, b_in, nullptr,
        nullptr, nullptr, nullptr, 0);

    // 3) LSTM layers (fused cell epilogues, permuted gate layout)
    for (int l = 0; l < 3; l++) {
        float* Xin  = (l & 1) ? X1 : X0;
        float* Xout = (l & 1) ? X0 : X1;
        // input proj (+ bias, + t==0 cell): gates in bufA (permuted cols)
        bgemm_kernel<4><<<dim3(8, NROWS / 128), 256>>>(
            Xin, INDIM, WihP + (size_t)l * 1024 * 256, INDIM,
            bufA, 1024, INDIM, biasP + l * 1024, nullptr,
            h2 /* t0 -> buffer 0 */, c, Xout, 0);
        for (int t = 1; t < 6; t++) {
            float* hin  = h2 + ((t + 1) & 1) * (NBM * HID);
            float* hout = h2 + (t & 1) * (NBM * HID);
            bgemm_kernel<5><<<dim3(8, NBM / 128), 256>>>(
                hin, HID, WhhP + (size_t)l * 1024 * 256, HID,
                bufA + t * 1024, NVIEW * 1024, HID, nullptr, nullptr,
                hout, c, Xout, t);
        }
    }

    // 4) heads + reduction (last layer output = X1)
    final1_kernel<<<NBM / 8, 256>>>(X1, Wv, bv, Ws, bs, score);
    final2_kernel<<<32, 256>>>(score, out);
}

// round 9
// speedup vs baseline: 1.3288x; 1.3288x over previous
#include <cuda_runtime.h>
#include <cuda_bf16.h>
#include <math.h>

// Problem constants
#define EMBED  1024
#define INDIM  256
#define HID    256
#define NVIEW  6
#define NROWS  49152   // B*M*NVIEW
#define NBM    8192    // B*M

#define LDSK32 20              // u32 per smem row (32 data bf16-pairs + pad)
#define STAGE_U32 (128 * LDSK32)

// Scratch (allocation-free: __device__ globals)
__device__ float g_bufA[(size_t)NROWS * EMBED];
__device__ float g_bufX[(size_t)NROWS * INDIM];
__device__ float g_h[NBM * HID];
__device__ float g_c[NBM * HID];
__device__ float g_score[NBM];

__device__ __forceinline__ void mma16816(float* d, const unsigned* a, const unsigned* b)
{
    asm volatile(
        "mma.sync.aligned.m16n8k16.row.col.f32.bf16.bf16.f32 "
        "{%0,%1,%2,%3}, {%4,%5,%6,%7}, {%8,%9}, {%0,%1,%2,%3};\n"
        : "+f"(d[0]), "+f"(d[1]), "+f"(d[2]), "+f"(d[3])
        : "r"(a[0]), "r"(a[1]), "r"(a[2]), "r"(a[3]), "r"(b[0]), "r"(b[1]));
}

__device__ __forceinline__ void ldsm_x4(unsigned& r0, unsigned& r1, unsigned& r2,
                                        unsigned& r3, unsigned addr)
{
    asm volatile("ldmatrix.sync.aligned.m8n8.x4.shared.b16 {%0,%1,%2,%3}, [%4];\n"
                 : "=r"(r0), "=r"(r1), "=r"(r2), "=r"(r3) : "r"(addr));
}

// Convert float4 (k..k+3 of one row) into hi/lo bf16 pairs in smem stage.
// Row layout (u32): [0..7] hi (16 bf16), [8..15] lo, [16..19] pad.
__device__ __forceinline__ void cvt_store(unsigned* S32, int row, int kc, float4 v)
{
    __nv_bfloat16 hx = __float2bfloat16_rn(v.x);
    __nv_bfloat16 hy = __float2bfloat16_rn(v.y);
    __nv_bfloat16 hz = __float2bfloat16_rn(v.z);
    __nv_bfloat16 hw = __float2bfloat16_rn(v.w);
    __nv_bfloat162 h01; h01.x = hx; h01.y = hy;
    __nv_bfloat162 h23; h23.x = hz; h23.y = hw;
    __nv_bfloat162 l01;
    l01.x = __float2bfloat16_rn(v.x - __bfloat162float(hx));
    l01.y = __float2bfloat16_rn(v.y - __bfloat162float(hy));
    __nv_bfloat162 l23;
    l23.x = __float2bfloat16_rn(v.z - __bfloat162float(hz));
    l23.y = __float2bfloat16_rn(v.w - __bfloat162float(hw));
    const int base = row * LDSK32 + (kc >> 1);
    uint2 hi; hi.x = *reinterpret_cast<unsigned*>(&h01); hi.y = *reinterpret_cast<unsigned*>(&h23);
    uint2 lo; lo.x = *reinterpret_cast<unsigned*>(&l01); lo.y = *reinterpret_cast<unsigned*>(&l23);
    *reinterpret_cast<uint2*>(S32 + base)     = hi;
    *reinterpret_cast<uint2*>(S32 + base + 8) = lo;
}

// ---------------------------------------------------------------------------
// C = A @ B^T via bf16x3-split tensor-core MMA. Tile 128x128x16, 8 warps
// (2Mx4N), warp tile 64x32. Double-buffered smem, ldmatrix fragment loads
// with cross-pass operand reuse: 12 LDSM.x4 per k-iter (Bh/Bl loaded once,
// Al overwrites Ah registers after Ah's last use).
// EPI 0: C = resid + gelu_exact(acc+bias0)   EPI 1: C = acc+bias0
// EPI 2: C = acc+bias0+bias1                 EPI 3: C += acc
// ---------------------------------------------------------------------------
template <int EPI>
__global__ __launch_bounds__(256, 2) void bgemm_kernel(
    const float* __restrict__ A, int lda,
    const float* __restrict__ B, int ldb,
    float* __restrict__ C, int ldc,
    int K,
    const float* __restrict__ bias0,
    const float* __restrict__ bias1,
    const float* __restrict__ resid)
{
    __shared__ __align__(16) unsigned As32[2 * STAGE_U32];
    __shared__ __align__(16) unsigned Bs32[2 * STAGE_U32];

    const int tid  = threadIdx.x;
    const int bx   = blockIdx.x;
    const int by   = blockIdx.y;
    const int warp = tid >> 5;
    const int lane = tid & 31;
    const int g    = lane >> 2;
    const int tg   = lane & 3;
    const int warpM = (warp & 1) * 64;
    const int warpN = (warp >> 1) * 32;

    // global loader mapping
    const int lrow = tid >> 2;
    const int kc   = (tid & 3) * 4;

    const float* Ap = A + (size_t)(by * 128 + lrow) * lda + kc;
    const float* Bp = B + (size_t)(bx * 128 + lrow) * ldb + kc;

    // ldmatrix lane addresses (bytes into smem)
    const unsigned asmem = (unsigned)__cvta_generic_to_shared(As32);
    const unsigned bsmem = (unsigned)__cvta_generic_to_shared(Bs32);
    unsigned aAddr[4], bAddr[2];
#pragma unroll
    for (int mt = 0; mt < 4; mt++) {
        const int r = warpM + mt * 16 + (lane & 15);
        aAddr[mt] = asmem + r * (LDSK32 * 4) + ((lane >> 4) & 1) * 16;
    }
#pragma unroll
    for (int p = 0; p < 2; p++) {
        const int r = warpN + p * 16 + (lane & 7) + ((lane >> 4) & 1) * 8;
        bAddr[p] = bsmem + r * (LDSK32 * 4) + ((lane >> 3) & 1) * 16;
    }

    float acc[4][4][4];
#pragma unroll
    for (int mt = 0; mt < 4; mt++)
#pragma unroll
        for (int nt = 0; nt < 4; nt++)
#pragma unroll
            for (int e = 0; e < 4; e++) acc[mt][nt][e] = 0.f;

    // prologue: load + convert k-chunk 0 into stage 0
    float4 pa0 = *reinterpret_cast<const float4*>(Ap);
    float4 pa1 = *reinterpret_cast<const float4*>(Ap + (size_t)64 * lda);
    float4 pb0 = *reinterpret_cast<const float4*>(Bp);
    float4 pb1 = *reinterpret_cast<const float4*>(Bp + (size_t)64 * ldb);
    cvt_store(As32, lrow,      kc, pa0);
    cvt_store(As32, lrow + 64, kc, pa1);
    cvt_store(Bs32, lrow,      kc, pb0);
    cvt_store(Bs32, lrow + 64, kc, pb1);
    __syncthreads();

    int stage = 0;
    for (int k0 = 0; k0 < K; k0 += 16) {
        const bool hasNext = (k0 + 16 < K);
        if (hasNext) {  // issue global loads early; complete under MMAs
            pa0 = *reinterpret_cast<const float4*>(Ap + k0 + 16);
            pa1 = *reinterpret_cast<const float4*>(Ap + (size_t)64 * lda + k0 + 16);
            pb0 = *reinterpret_cast<const float4*>(Bp + k0 + 16);
            pb1 = *reinterpret_cast<const float4*>(Bp + (size_t)64 * ldb + k0 + 16);
        }

        const unsigned soff = stage * (STAGE_U32 * 4);
        // Split passes with reuse: (Ah,Bh) -> (Ah,Bl) -> (Al,Bh).
        // ahl holds Ah for passes 0-1, then is overwritten with Al for pass 2.
        {
            unsigned ahl[4][4], bh[4][2], bl[4][2];
#pragma unroll
            for (int mt = 0; mt < 4; mt++)
                ldsm_x4(ahl[mt][0], ahl[mt][1], ahl[mt][2], ahl[mt][3],
                        aAddr[mt] + soff);
            ldsm_x4(bh[0][0], bh[0][1], bh[1][0], bh[1][1], bAddr[0] + soff);
            ldsm_x4(bh[2][0], bh[2][1], bh[3][0], bh[3][1], bAddr[1] + soff);
            ldsm_x4(bl[0][0], bl[0][1], bl[1][0], bl[1][1], bAddr[0] + soff + 32u);
            ldsm_x4(bl[2][0], bl[2][1], bl[3][0], bl[3][1], bAddr[1] + soff + 32u);
#pragma unroll
            for (int mt = 0; mt < 4; mt++)
#pragma unroll
                for (int nt = 0; nt < 4; nt++)
                    mma16816(acc[mt][nt], ahl[mt], bh[nt]);
#pragma unroll
            for (int mt = 0; mt < 4; mt++)
#pragma unroll
                for (int nt = 0; nt < 4; nt++)
                    mma16816(acc[mt][nt], ahl[mt], bl[nt]);
#pragma unroll
            for (int mt = 0; mt < 4; mt++)
                ldsm_x4(ahl[mt][0], ahl[mt][1], ahl[mt][2], ahl[mt][3],
                        aAddr[mt] + soff + 32u);
#pragma unroll
            for (int mt = 0; mt < 4; mt++)
#pragma unroll
                for (int nt = 0; nt < 4; nt++)
                    mma16816(acc[mt][nt], ahl[mt], bh[nt]);
        }

        if (hasNext) {
            unsigned* An = As32 + (stage ^ 1) * STAGE_U32;
            unsigned* Bn = Bs32 + (stage ^ 1) * STAGE_U32;
            cvt_store(An, lrow,      kc, pa0);
            cvt_store(An, lrow + 64, kc, pa1);
            cvt_store(Bn, lrow,      kc, pb0);
            cvt_store(Bn, lrow + 64, kc, pb1);
            stage ^= 1;
            __syncthreads();
        }
    }

    // epilogue (float2-vectorized: col pairs are contiguous)
#pragma unroll
    for (int mt = 0; mt < 4; mt++) {
#pragma unroll
        for (int nt = 0; nt < 4; nt++) {
            const float* d = acc[mt][nt];
            const int gc = bx * 128 + warpN + nt * 8 + tg * 2;
#pragma unroll
            for (int half = 0; half < 2; half++) {
                const int gr = by * 128 + warpM + mt * 16 + g + half * 8;
                float* cp = C + (size_t)gr * ldc + gc;
                float2 v; v.x = d[half * 2]; v.y = d[half * 2 + 1];
                if (EPI == 0) {
                    v.x += bias0[gc]; v.y += bias0[gc + 1];
                    float2 rs = *reinterpret_cast<const float2*>(
                        resid + (size_t)gr * ldc + gc);
                    v.x = 0.5f * v.x * (1.f + erff(v.x * 0.70710678118654752f)) + rs.x;
                    v.y = 0.5f * v.y * (1.f + erff(v.y * 0.70710678118654752f)) + rs.y;
                } else if (EPI == 1) {
                    v.x += bias0[gc]; v.y += bias0[gc + 1];
                } else if (EPI == 2) {
                    v.x += bias0[gc] + bias1[gc]; v.y += bias0[gc + 1] + bias1[gc + 1];
                } else {
                    float2 old = *reinterpret_cast<const float2*>(cp);
                    v.x += old.x; v.y += old.y;
                }
                *reinterpret_cast<float2*>(cp) = v;
            }
        }
    }
}

// ---------------------------------------------------------------------------
// LSTM pointwise cell update, float4-vectorized (4 hidden units / thread).
// ---------------------------------------------------------------------------
__global__ __launch_bounds__(256) void lstm_cell_kernel(
    const float* __restrict__ gb, float* __restrict__ h, float* __restrict__ c,
    float* __restrict__ X, int t, int first)
{
    const int idx4 = blockIdx.x * blockDim.x + threadIdx.x;  // NBM*64
    const int bm = idx4 >> 6;
    const int j4 = (idx4 & 63) * 4;
    const float* g = gb + (size_t)(bm * 6 + t) * 1024;
    const float4 gi = *reinterpret_cast<const float4*>(g + j4);
    const float4 gf = *reinterpret_cast<const float4*>(g + 256 + j4);
    const float4 gg = *reinterpret_cast<const float4*>(g + 512 + j4);
    const float4 go = *reinterpret_cast<const float4*>(g + 768 + j4);
    float4 cold;
    if (first) { cold.x = cold.y = cold.z = cold.w = 0.f; }
    else cold = *reinterpret_cast<const float4*>(c + bm * 256 + j4);
    float4 cn, hn;
#define CELL(e) { \
    float si = 1.f / (1.f + expf(-gi.e)); \
    float sf = 1.f / (1.f + expf(-gf.e)); \
    float so = 1.f / (1.f + expf(-go.e)); \
    cn.e = sf * cold.e + si * tanhf(gg.e); \
    hn.e = so * tanhf(cn.e); }
    CELL(x) CELL(y) CELL(z) CELL(w)
#undef CELL
    *reinterpret_cast<float4*>(c + bm * 256 + j4) = cn;
    *reinterpret_cast<float4*>(h + bm * 256 + j4) = hn;
    *reinterpret_cast<float4*>(X + (size_t)(bm * 6 + t) * 256 + j4) = hn;
}

__global__ __launch_bounds__(256) void final1_kernel(
    const float* __restrict__ X, const float* __restrict__ Wv,
    const float* __restrict__ bv, const float* __restrict__ Ws,
    const float* __restrict__ bs, float* __restrict__ score)
{
    const int warp = threadIdx.x >> 5;
    const int lane = threadIdx.x & 31;
    const int bm = blockIdx.x * 8 + warp;
    float wv[8];
#pragma unroll
    for (int u = 0; u < 8; u++) wv[u] = Wv[lane + u * 32];
    float acc = 0.f;
#pragma unroll
    for (int t = 0; t < 6; t++) {
        const float* row = X + (size_t)(bm * 6 + t) * 256;
        float p = 0.f;
#pragma unroll
        for (int u = 0; u < 8; u++) p = fmaf(row[lane + u * 32], wv[u], p);
#pragma unroll
        for (int o = 16; o; o >>= 1) p += __shfl_xor_sync(0xFFFFFFFFu, p, o);
        acc = fmaf(Ws[t], p + bv[0], acc);
    }
    if (lane == 0) score[bm] = acc + bs[0];
}

__global__ __launch_bounds__(256) void final2_kernel(
    const float* __restrict__ score, float* __restrict__ out)
{
    __shared__ float s[256];
    s[threadIdx.x] = score[blockIdx.x * 256 + threadIdx.x];
    __syncthreads();
    for (int o = 128; o; o >>= 1) {
        if (threadIdx.x < o) s[threadIdx.x] += s[threadIdx.x + o];
        __syncthreads();
    }
    if (threadIdx.x == 0) out[blockIdx.x] = s[0] * (1.f / 256.f);
}

extern "C" void kernel_launch(void* const* d_in, const int* in_sizes, int n_in,
                              void* d_out, int out_size)
{
    (void)in_sizes; (void)n_in; (void)out_size;
    const float* swin = (const float*)d_in[0];
    const float* conv = (const float*)d_in[1];
    const float* Wc   = (const float*)d_in[2];
    const float* bc   = (const float*)d_in[3];
    const float* Win  = (const float*)d_in[4];
    const float* b_in = (const float*)d_in[5];
    const float* Wih  = (const float*)d_in[6];
    const float* Whh  = (const float*)d_in[7];
    const float* bih  = (const float*)d_in[8];
    const float* bhh  = (const float*)d_in[9];
    const float* Wv   = (const float*)d_in[10];
    const float* bv   = (const float*)d_in[11];
    const float* Ws   = (const float*)d_in[12];
    const float* bs   = (const float*)d_in[13];
    float* out = (float*)d_out;

    float *bufA, *bufX, *h, *c, *score;
    cudaGetSymbolAddress((void**)&bufA, g_bufA);
    cudaGetSymbolAddress((void**)&bufX, g_bufX);
    cudaGetSymbolAddress((void**)&h, g_h);
    cudaGetSymbolAddress((void**)&c, g_c);
    cudaGetSymbolAddress((void**)&score, g_score);

    // 1) bufA = swin + gelu(conv @ Wc^T + bc)   [49152,1024]
    bgemm_kernel<0><<<dim3(EMBED / 128, NROWS / 128), 256>>>(
        conv, EMBED, Wc, EMBED, bufA, EMBED, EMBED, bc, nullptr, swin);

    // 2) bufX = bufA @ Win^T + b_in             [49152,256]
    bgemm_kernel<1><<<dim3(INDIM / 128, NROWS / 128), 256>>>(
        bufA, EMBED, Win, EMBED, bufX, INDIM, EMBED, b_in, nullptr, nullptr);

    // 3) LSTM layers
    for (int l = 0; l < 3; l++) {
        const float* WihL = Wih + (size_t)l * 4 * HID * INDIM;
        const float* WhhL = Whh + (size_t)l * 4 * HID * HID;
        bgemm_kernel<2><<<dim3(4 * HID / 128, NROWS / 128), 256>>>(
            bufX, INDIM, WihL, INDIM, bufA, 4 * HID, INDIM,
            bih + l * 4 * HID, bhh + l * 4 * HID, nullptr);
        for (int t = 0; t < 6; t++) {
            if (t > 0) {
                bgemm_kernel<3><<<dim3(4 * HID / 128, NBM / 128), 256>>>(
                    h, HID, WhhL, HID, bufA + t * 4 * HID, NVIEW * 4 * HID, HID,
                    nullptr, nullptr, nullptr);
            }
            lstm_cell_kernel<<<NBM * 64 / 256, 256>>>(bufA, h, c, bufX, t, t == 0 ? 1 : 0);
        }
    }

    // 4) heads + reduction
    final1_kernel<<<NBM / 8, 256>>>(bufX, Wv, bv, Ws, bs, score);
    final2_kernel<<<32, 256>>>(score, out);
}

// round 14
// speedup vs baseline: 1.4267x; 1.0737x over previous
#include <cuda_runtime.h>
#include <cuda_bf16.h>
#include <cuda_fp16.h>
#include <stdint.h>
#include <math.h>

// Problem constants
#define EMBED  1024
#define INDIM  256
#define HID    256
#define NVIEW  6
#define NROWS  49152   // B*M*NVIEW
#define NBM    8192    // B*M

#define LDSK32 20              // u32 per smem row (32 data bf16-pairs + pad)
#define STAGE_U32 (128 * LDSK32)

// Scratch (allocation-free: __device__ globals)
__device__ float g_bufA[(size_t)NROWS * EMBED];
__device__ float g_bufX[(size_t)NROWS * INDIM];
__device__ float g_h[NBM * HID];
__device__ float g_c[NBM * HID];
__device__ float g_score[NBM];

__device__ __forceinline__ void mma_bf16(float* d, const unsigned* a, const unsigned* b)
{
    asm volatile(
        "mma.sync.aligned.m16n8k16.row.col.f32.bf16.bf16.f32 "
        "{%0,%1,%2,%3}, {%4,%5,%6,%7}, {%8,%9}, {%0,%1,%2,%3};\n"
        : "+f"(d[0]), "+f"(d[1]), "+f"(d[2]), "+f"(d[3])
        : "r"(a[0]), "r"(a[1]), "r"(a[2]), "r"(a[3]), "r"(b[0]), "r"(b[1]));
}

__device__ __forceinline__ void mma_fp16(float* d, const unsigned* a, const unsigned* b)
{
    asm volatile(
        "mma.sync.aligned.m16n8k16.row.col.f32.f16.f16.f32 "
        "{%0,%1,%2,%3}, {%4,%5,%6,%7}, {%8,%9}, {%0,%1,%2,%3};\n"
        : "+f"(d[0]), "+f"(d[1]), "+f"(d[2]), "+f"(d[3])
        : "r"(a[0]), "r"(a[1]), "r"(a[2]), "r"(a[3]), "r"(b[0]), "r"(b[1]));
}

__device__ __forceinline__ void ldsm_x4(unsigned& r0, unsigned& r1, unsigned& r2,
                                        unsigned& r3, unsigned addr)
{
    asm volatile("ldmatrix.sync.aligned.m8n8.x4.shared.b16 {%0,%1,%2,%3}, [%4];\n"
                 : "=r"(r0), "=r"(r1), "=r"(r2), "=r"(r3) : "r"(addr));
}

// ---- bf16 hi/lo convert+store (rows: u32 [0..7]=hi, [8..15]=lo, pad) ----
__device__ __forceinline__ void cvt_store(unsigned* S32, int row, int kc, float4 v)
{
    __nv_bfloat16 hx = __float2bfloat16_rn(v.x);
    __nv_bfloat16 hy = __float2bfloat16_rn(v.y);
    __nv_bfloat16 hz = __float2bfloat16_rn(v.z);
    __nv_bfloat16 hw = __float2bfloat16_rn(v.w);
    __nv_bfloat162 h01; h01.x = hx; h01.y = hy;
    __nv_bfloat162 h23; h23.x = hz; h23.y = hw;
    __nv_bfloat162 l01;
    l01.x = __float2bfloat16_rn(v.x - __bfloat162float(hx));
    l01.y = __float2bfloat16_rn(v.y - __bfloat162float(hy));
    __nv_bfloat162 l23;
    l23.x = __float2bfloat16_rn(v.z - __bfloat162float(hz));
    l23.y = __float2bfloat16_rn(v.w - __bfloat162float(hw));
    const int base = row * LDSK32 + (kc >> 1);
    uint2 hi; hi.x = *reinterpret_cast<unsigned*>(&h01); hi.y = *reinterpret_cast<unsigned*>(&h23);
    uint2 lo; lo.x = *reinterpret_cast<unsigned*>(&l01); lo.y = *reinterpret_cast<unsigned*>(&l23);
    *reinterpret_cast<uint2*>(S32 + base)     = hi;
    *reinterpret_cast<uint2*>(S32 + base + 8) = lo;
}

// ---- fp16 hi/lo (A) and fp16 hi-only (B) converts ----
__device__ __forceinline__ void cvt_store_h2(unsigned* S32, int row, int kc, float4 v)
{
    __half hx = __float2half_rn(v.x), hy = __float2half_rn(v.y);
    __half hz = __float2half_rn(v.z), hw = __float2half_rn(v.w);
    __half2 h01; h01.x = hx; h01.y = hy;
    __half2 h23; h23.x = hz; h23.y = hw;
    __half2 l01;
    l01.x = __float2half_rn(v.x - __half2float(hx));
    l01.y = __float2half_rn(v.y - __half2float(hy));
    __half2 l23;
    l23.x = __float2half_rn(v.z - __half2float(hz));
    l23.y = __float2half_rn(v.w - __half2float(hw));
    const int base = row * LDSK32 + (kc >> 1);
    uint2 hi; hi.x = *reinterpret_cast<unsigned*>(&h01); hi.y = *reinterpret_cast<unsigned*>(&h23);
    uint2 lo; lo.x = *reinterpret_cast<unsigned*>(&l01); lo.y = *reinterpret_cast<unsigned*>(&l23);
    *reinterpret_cast<uint2*>(S32 + base)     = hi;
    *reinterpret_cast<uint2*>(S32 + base + 8) = lo;
}
__device__ __forceinline__ void cvt_store_h1(unsigned* S32, int row, int kc, float4 v)
{
    __half2 h01; h01.x = __float2half_rn(v.x); h01.y = __float2half_rn(v.y);
    __half2 h23; h23.x = __float2half_rn(v.z); h23.y = __float2half_rn(v.w);
    const int base = row * LDSK32 + (kc >> 1);
    uint2 hi; hi.x = *reinterpret_cast<unsigned*>(&h01); hi.y = *reinterpret_cast<unsigned*>(&h23);
    *reinterpret_cast<uint2*>(S32 + base) = hi;
}

// ---------------------------------------------------------------------------
// bf16x3 tensor-core GEMM (R7 winner, unchanged). C = A @ B^T.
// EPI 1: C = acc+bias0   EPI 2: C = acc+bias0+bias1   EPI 3: C += acc
// ---------------------------------------------------------------------------
template <int EPI>
__global__ __launch_bounds__(256, 2) void bgemm_kernel(
    const float* __restrict__ A, int lda,
    const float* __restrict__ B, int ldb,
    float* __restrict__ C, int ldc,
    int K,
    const float* __restrict__ bias0,
    const float* __restrict__ bias1,
    const float* __restrict__ resid)
{
    __shared__ __align__(16) unsigned As32[2 * STAGE_U32];
    __shared__ __align__(16) unsigned Bs32[2 * STAGE_U32];

    const int tid  = threadIdx.x;
    const int bx   = blockIdx.x;
    const int by   = blockIdx.y;
    const int warp = tid >> 5;
    const int lane = tid & 31;
    const int g    = lane >> 2;
    const int tg   = lane & 3;
    const int warpM = (warp & 1) * 64;
    const int warpN = (warp >> 1) * 32;
    const int lrow = tid >> 2;
    const int kc   = (tid & 3) * 4;

    const float* Ap = A + (size_t)(by * 128 + lrow) * lda + kc;
    const float* Bp = B + (size_t)(bx * 128 + lrow) * ldb + kc;

    const unsigned asmem = (unsigned)__cvta_generic_to_shared(As32);
    const unsigned bsmem = (unsigned)__cvta_generic_to_shared(Bs32);
    unsigned aAddr[4], bAddr[2];
#pragma unroll
    for (int mt = 0; mt < 4; mt++) {
        const int r = warpM + mt * 16 + (lane & 15);
        aAddr[mt] = asmem + r * (LDSK32 * 4) + ((lane >> 4) & 1) * 16;
    }
#pragma unroll
    for (int p = 0; p < 2; p++) {
        const int r = warpN + p * 16 + (lane & 7) + ((lane >> 4) & 1) * 8;
        bAddr[p] = bsmem + r * (LDSK32 * 4) + ((lane >> 3) & 1) * 16;
    }

    float acc[4][4][4];
#pragma unroll
    for (int mt = 0; mt < 4; mt++)
#pragma unroll
        for (int nt = 0; nt < 4; nt++)
#pragma unroll
            for (int e = 0; e < 4; e++) acc[mt][nt][e] = 0.f;

    float4 pa0 = *reinterpret_cast<const float4*>(Ap);
    float4 pa1 = *reinterpret_cast<const float4*>(Ap + (size_t)64 * lda);
    float4 pb0 = *reinterpret_cast<const float4*>(Bp);
    float4 pb1 = *reinterpret_cast<const float4*>(Bp + (size_t)64 * ldb);
    cvt_store(As32, lrow,      kc, pa0);
    cvt_store(As32, lrow + 64, kc, pa1);
    cvt_store(Bs32, lrow,      kc, pb0);
    cvt_store(Bs32, lrow + 64, kc, pb1);
    __syncthreads();

    int stage = 0;
    for (int k0 = 0; k0 < K; k0 += 16) {
        const bool hasNext = (k0 + 16 < K);
        if (hasNext) {
            pa0 = *reinterpret_cast<const float4*>(Ap + k0 + 16);
            pa1 = *reinterpret_cast<const float4*>(Ap + (size_t)64 * lda + k0 + 16);
            pb0 = *reinterpret_cast<const float4*>(Bp + k0 + 16);
            pb1 = *reinterpret_cast<const float4*>(Bp + (size_t)64 * ldb + k0 + 16);
        }
        const unsigned soff = stage * (STAGE_U32 * 4);
#pragma unroll
        for (int s = 0; s < 3; s++) {
            const unsigned ao = (s == 1) ? 32u : 0u;
            const unsigned bo = (s == 2) ? 32u : 0u;
            unsigned af[4][4], bfr[4][2];
#pragma unroll
            for (int mt = 0; mt < 4; mt++)
                ldsm_x4(af[mt][0], af[mt][1], af[mt][2], af[mt][3],
                        aAddr[mt] + soff + ao);
            ldsm_x4(bfr[0][0], bfr[0][1], bfr[1][0], bfr[1][1], bAddr[0] + soff + bo);
            ldsm_x4(bfr[2][0], bfr[2][1], bfr[3][0], bfr[3][1], bAddr[1] + soff + bo);
#pragma unroll
            for (int mt = 0; mt < 4; mt++)
#pragma unroll
                for (int nt = 0; nt < 4; nt++)
                    mma_bf16(acc[mt][nt], af[mt], bfr[nt]);
        }
        if (hasNext) {
            unsigned* An = As32 + (stage ^ 1) * STAGE_U32;
            unsigned* Bn = Bs32 + (stage ^ 1) * STAGE_U32;
            cvt_store(An, lrow,      kc, pa0);
            cvt_store(An, lrow + 64, kc, pa1);
            cvt_store(Bn, lrow,      kc, pb0);
            cvt_store(Bn, lrow + 64, kc, pb1);
            stage ^= 1;
            __syncthreads();
        }
    }

#pragma unroll
    for (int mt = 0; mt < 4; mt++) {
#pragma unroll
        for (int nt = 0; nt < 4; nt++) {
            const float* d = acc[mt][nt];
            const int gc = bx * 128 + warpN + nt * 8 + tg * 2;
#pragma unroll
            for (int half = 0; half < 2; half++) {
                const int gr = by * 128 + warpM + mt * 16 + g + half * 8;
                float* cp = C + (size_t)gr * ldc + gc;
                float2 v; v.x = d[half * 2]; v.y = d[half * 2 + 1];
                if (EPI == 1) {
                    v.x += bias0[gc]; v.y += bias0[gc + 1];
                } else if (EPI == 2) {
                    v.x += bias0[gc] + bias1[gc]; v.y += bias0[gc + 1] + bias1[gc + 1];
                } else {
                    float2 old = *reinterpret_cast<const float2*>(cp);
                    v.x += old.x; v.y += old.y;
                }
                *reinterpret_cast<float2*>(cp) = v;
            }
        }
    }
}

// ---------------------------------------------------------------------------
// fp16 2-pass GEMM for GEMM1: C = resid + gelu(A@B^T + bias0).
// A split fp16 hi+lo (exact to ~2^-22); B single fp16 (weights, ~2.8e-4 rms).
// ---------------------------------------------------------------------------
__global__ __launch_bounds__(256, 2) void hgemm_gelu_kernel(
    const float* __restrict__ A, int lda,
    const float* __restrict__ B, int ldb,
    float* __restrict__ C, int ldc,
    int K,
    const float* __restrict__ bias0,
    const float* __restrict__ resid)
{
    __shared__ __align__(16) unsigned As32[2 * STAGE_U32];
    __shared__ __align__(16) unsigned Bs32[2 * STAGE_U32];

    const int tid  = threadIdx.x;
    const int bx   = blockIdx.x;
    const int by   = blockIdx.y;
    const int warp = tid >> 5;
    const int lane = tid & 31;
    const int g    = lane >> 2;
    const int tg   = lane & 3;
    const int warpM = (warp & 1) * 64;
    const int warpN = (warp >> 1) * 32;
    const int lrow = tid >> 2;
    const int kc   = (tid & 3) * 4;

    const float* Ap = A + (size_t)(by * 128 + lrow) * lda + kc;
    const float* Bp = B + (size_t)(bx * 128 + lrow) * ldb + kc;

    const unsigned asmem = (unsigned)__cvta_generic_to_shared(As32);
    const unsigned bsmem = (unsigned)__cvta_generic_to_shared(Bs32);
    unsigned aAddr[4], bAddr[2];
#pragma unroll
    for (int mt = 0; mt < 4; mt++) {
        const int r = warpM + mt * 16 + (lane & 15);
        aAddr[mt] = asmem + r * (LDSK32 * 4) + ((lane >> 4) & 1) * 16;
    }
#pragma unroll
    for (int p = 0; p < 2; p++) {
        const int r = warpN + p * 16 + (lane & 7) + ((lane >> 4) & 1) * 8;
        bAddr[p] = bsmem + r * (LDSK32 * 4) + ((lane >> 3) & 1) * 16;
    }

    float acc[4][4][4];
#pragma unroll
    for (int mt = 0; mt < 4; mt++)
#pragma unroll
        for (int nt = 0; nt < 4; nt++)
#pragma unroll
            for (int e = 0; e < 4; e++) acc[mt][nt][e] = 0.f;

    float4 pa0 = *reinterpret_cast<const float4*>(Ap);
    float4 pa1 = *reinterpret_cast<const float4*>(Ap + (size_t)64 * lda);
    float4 pb0 = *reinterpret_cast<const float4*>(Bp);
    float4 pb1 = *reinterpret_cast<const float4*>(Bp + (size_t)64 * ldb);
    cvt_store_h2(As32, lrow,      kc, pa0);
    cvt_store_h2(As32, lrow + 64, kc, pa1);
    cvt_store_h1(Bs32, lrow,      kc, pb0);
    cvt_store_h1(Bs32, lrow + 64, kc, pb1);
    __syncthreads();

    int stage = 0;
    for (int k0 = 0; k0 < K; k0 += 16) {
        const bool hasNext = (k0 + 16 < K);
        if (hasNext) {
            pa0 = *reinterpret_cast<const float4*>(Ap + k0 + 16);
            pa1 = *reinterpret_cast<const float4*>(Ap + (size_t)64 * lda + k0 + 16);
            pb0 = *reinterpret_cast<const float4*>(Bp + k0 + 16);
            pb1 = *reinterpret_cast<const float4*>(Bp + (size_t)64 * ldb + k0 + 16);
        }
        const unsigned soff = stage * (STAGE_U32 * 4);
        {
            unsigned af[4][4], bfr[4][2];
            // pass 0: Ah x Bh
#pragma unroll
            for (int mt = 0; mt < 4; mt++)
                ldsm_x4(af[mt][0], af[mt][1], af[mt][2], af[mt][3], aAddr[mt] + soff);
            ldsm_x4(bfr[0][0], bfr[0][1], bfr[1][0], bfr[1][1], bAddr[0] + soff);
            ldsm_x4(bfr[2][0], bfr[2][1], bfr[3][0], bfr[3][1], bAddr[1] + soff);
#pragma unroll
            for (int mt = 0; mt < 4; mt++)
#pragma unroll
                for (int nt = 0; nt < 4; nt++)
                    mma_fp16(acc[mt][nt], af[mt], bfr[nt]);
            // pass 1: Al x Bh (reuse Bh fragments)
#pragma unroll
            for (int mt = 0; mt < 4; mt++)
                ldsm_x4(af[mt][0], af[mt][1], af[mt][2], af[mt][3],
                        aAddr[mt] + soff + 32u);
#pragma unroll
            for (int mt = 0; mt < 4; mt++)
#pragma unroll
                for (int nt = 0; nt < 4; nt++)
                    mma_fp16(acc[mt][nt], af[mt], bfr[nt]);
        }
        if (hasNext) {
            unsigned* An = As32 + (stage ^ 1) * STAGE_U32;
            unsigned* Bn = Bs32 + (stage ^ 1) * STAGE_U32;
            cvt_store_h2(An, lrow,      kc, pa0);
            cvt_store_h2(An, lrow + 64, kc, pa1);
            cvt_store_h1(Bn, lrow,      kc, pb0);
            cvt_store_h1(Bn, lrow + 64, kc, pb1);
            stage ^= 1;
            __syncthreads();
        }
    }

#pragma unroll
    for (int mt = 0; mt < 4; mt++) {
#pragma unroll
        for (int nt = 0; nt < 4; nt++) {
            const float* d = acc[mt][nt];
            const int gc = bx * 128 + warpN + nt * 8 + tg * 2;
#pragma unroll
            for (int half = 0; half < 2; half++) {
                const int gr = by * 128 + warpM + mt * 16 + g + half * 8;
                float* cp = C + (size_t)gr * ldc + gc;
                float2 v; v.x = d[half * 2]; v.y = d[half * 2 + 1];
                v.x += bias0[gc]; v.y += bias0[gc + 1];
                float2 rs = *reinterpret_cast<const float2*>(
                    resid + (size_t)gr * ldc + gc);
                v.x = 0.5f * v.x * (1.f + erff(v.x * 0.70710678118654752f)) + rs.x;
                v.y = 0.5f * v.y * (1.f + erff(v.y * 0.70710678118654752f)) + rs.y;
                *reinterpret_cast<float2*>(cp) = v;
            }
        }
    }
}

// ---------------------------------------------------------------------------
// LSTM pointwise cell update, float4-vectorized (4 hidden units / thread).
// ---------------------------------------------------------------------------
__global__ __launch_bounds__(256) void lstm_cell_kernel(
    const float* __restrict__ gb, float* __restrict__ h, float* __restrict__ c,
    float* __restrict__ X, int t, int first)
{
    const int idx4 = blockIdx.x * blockDim.x + threadIdx.x;  // NBM*64
    const int bm = idx4 >> 6;
    const int j4 = (idx4 & 63) * 4;
    const float* g = gb + (size_t)(bm * 6 + t) * 1024;
    const float4 gi = *reinterpret_cast<const float4*>(g + j4);
    const float4 gf = *reinterpret_cast<const float4*>(g + 256 + j4);
    const float4 gg = *reinterpret_cast<const float4*>(g + 512 + j4);
    const float4 go = *reinterpret_cast<const float4*>(g + 768 + j4);
    float4 cold;
    if (first) { cold.x = cold.y = cold.z = cold.w = 0.f; }
    else cold = *reinterpret_cast<const float4*>(c + bm * 256 + j4);
    float4 cn, hn;
#define CELL(e) { \
    float si = 1.f / (1.f + expf(-gi.e)); \
    float sf = 1.f / (1.f + expf(-gf.e)); \
    float so = 1.f / (1.f + expf(-go.e)); \
    cn.e = sf * cold.e + si * tanhf(gg.e); \
    hn.e = so * tanhf(cn.e); }
    CELL(x) CELL(y) CELL(z) CELL(w)
#undef CELL
    *reinterpret_cast<float4*>(c + bm * 256 + j4) = cn;
    *reinterpret_cast<float4*>(h + bm * 256 + j4) = hn;
    *reinterpret_cast<float4*>(X + (size_t)(bm * 6 + t) * 256 + j4) = hn;
}

__global__ __launch_bounds__(256) void final1_kernel(
    const float* __restrict__ X, const float* __restrict__ Wv,
    const float* __restrict__ bv, const float* __restrict__ Ws,
    const float* __restrict__ bs, float* __restrict__ score)
{
    const int warp = threadIdx.x >> 5;
    const int lane = threadIdx.x & 31;
    const int bm = blockIdx.x * 8 + warp;
    float wv[8];
#pragma unroll
    for (int u = 0; u < 8; u++) wv[u] = Wv[lane + u * 32];
    float acc = 0.f;
#pragma unroll
    for (int t = 0; t < 6; t++) {
        const float* row = X + (size_t)(bm * 6 + t) * 256;
        float p = 0.f;
#pragma unroll
        for (int u = 0; u < 8; u++) p = fmaf(row[lane + u * 32], wv[u], p);
#pragma unroll
        for (int o = 16; o; o >>= 1) p += __shfl_xor_sync(0xFFFFFFFFu, p, o);
        acc = fmaf(Ws[t], p + bv[0], acc);
    }
    if (lane == 0) score[bm] = acc + bs[0];
}

__global__ __launch_bounds__(256) void final2_kernel(
    const float* __restrict__ score, float* __restrict__ out)
{
    __shared__ float s[256];
    s[threadIdx.x] = score[blockIdx.x * 256 + threadIdx.x];
    __syncthreads();
    for (int o = 128; o; o >>= 1) {
        if (threadIdx.x < o) s[threadIdx.x] += s[threadIdx.x + o];
        __syncthreads();
    }
    if (threadIdx.x == 0) out[blockIdx.x] = s[0] * (1.f / 256.f);
}

extern "C" void kernel_launch(void* const* d_in, const int* in_sizes, int n_in,
                              void* d_out, int out_size)
{
    (void)in_sizes; (void)n_in; (void)out_size;
    const float* swin = (const float*)d_in[0];
    const float* conv = (const float*)d_in[1];
    const float* Wc   = (const float*)d_in[2];
    const float* bc   = (const float*)d_in[3];
    const float* Win  = (const float*)d_in[4];
    const float* b_in = (const float*)d_in[5];
    const float* Wih  = (const float*)d_in[6];
    const float* Whh  = (const float*)d_in[7];
    const float* bih  = (const float*)d_in[8];
    const float* bhh  = (const float*)d_in[9];
    const float* Wv   = (const float*)d_in[10];
    const float* bv   = (const float*)d_in[11];
    const float* Ws   = (const float*)d_in[12];
    const float* bs   = (const float*)d_in[13];
    float* out = (float*)d_out;

    float *bufA, *bufX, *h, *c, *score;
    cudaGetSymbolAddress((void**)&bufA, g_bufA);
    cudaGetSymbolAddress((void**)&bufX, g_bufX);
    cudaGetSymbolAddress((void**)&h, g_h);
    cudaGetSymbolAddress((void**)&c, g_c);
    cudaGetSymbolAddress((void**)&score, g_score);

    // 1) bufA = swin + gelu(conv @ Wc^T + bc)   [49152,1024]  (fp16 2-pass)
    hgemm_gelu_kernel<<<dim3(EMBED / 128, NROWS / 128), 256>>>(
        conv, EMBED, Wc, EMBED, bufA, EMBED, EMBED, bc, swin);

    // 2) bufX = bufA @ Win^T + b_in             [49152,256]  (bf16x3)
    bgemm_kernel<1><<<dim3(INDIM / 128, NROWS / 128), 256>>>(
        bufA, EMBED, Win, EMBED, bufX, INDIM, EMBED, b_in, nullptr, nullptr);

    // 3) LSTM layers (bf16x3)
    for (int l = 0; l < 3; l++) {
        const float* WihL = Wih + (size_t)l * 4 * HID * INDIM;
        const float* WhhL = Whh + (size_t)l * 4 * HID * HID;
        bgemm_kernel<2><<<dim3(4 * HID / 128, NROWS / 128), 256>>>(
            bufX, INDIM, WihL, INDIM, bufA, 4 * HID, INDIM,
            bih + l * 4 * HID, bhh + l * 4 * HID, nullptr);
        for (int t = 0; t < 6; t++) {
            if (t > 0) {
                bgemm_kernel<3><<<dim3(4 * HID / 128, NBM / 128), 256>>>(
                    h, HID, WhhL, HID, bufA + t * 4 * HID, NVIEW * 4 * HID, HID,
                    nullptr, nullptr, nullptr);
            }
            lstm_cell_kernel<<<NBM * 64 / 256, 256>>>(bufA, h, c, bufX, t, t == 0 ? 1 : 0);
        }
    }

    // 4) heads + reduction
    final1_kernel<<<NBM / 8, 256>>>(bufX, Wv, bv, Ws, bs, score);
    final2_kernel<<<32, 256>>>(score, out);
}